// round 5
// baseline (speedup 1.0000x reference)
#include <cuda_runtime.h>
#include <cuda_bf16.h>

// ---------------------------------------------------------------------------
// TensorizedEmbedding: out[b] = core0[d0] x core1[d1] x core2[d2] x core3[d3]
// ROW_DIMS=(8,10,20,20), COL_DIMS=(4,4,6,8), RANKS=(1,16,16,16,1)
// Strategy: pre-contract into T01[80][16r][16a] and T23[400][16r][48c],
// then per token a 16x48x16 GEMM from shared memory.
// Staging via LDG.128+STS.128 (keeps table slices L1-resident; cp.async.cg
// regressed by forcing the L2 path). Lane tile 4a x 6c (broadcast-heavy
// smem reads), packed f32x2 FMA, streaming output stores.
// ---------------------------------------------------------------------------

static __device__ float g_T01[80 * 256];    // [(d0*10+d1)][r2][a]  (a = m0*4+m1)
static __device__ float g_T23[400 * 768];   // [(d2*20+d3)][r2][c]  (c = m2*8+m3)

// Fused precompute: blocks 0..79 build T01, blocks 80..479 build T23.
__global__ void precompute_tables(const float* __restrict__ core0,
                                  const float* __restrict__ core1,
                                  const float* __restrict__ core2,
                                  const float* __restrict__ core3) {
    if (blockIdx.x < 80) {
        int comb = blockIdx.x;
        int d0 = comb / 10, d1 = comb % 10;
        int e  = threadIdx.x;             // 0..255
        int r2 = e >> 4;
        int a  = e & 15;                  // m0*4 + m1
        int m0 = a >> 2, m1 = a & 3;
        float s = 0.f;
#pragma unroll
        for (int r1 = 0; r1 < 16; ++r1) {
            float v0 = core0[(d0 * 4 + m0) * 16 + r1];             // [1,8,4,16]
            float v1 = core1[((r1 * 10 + d1) * 4 + m1) * 16 + r2]; // [16,10,4,16]
            s += v0 * v1;
        }
        g_T01[comb * 256 + r2 * 16 + a] = s;
    } else {
        int comb = blockIdx.x - 80;       // 0..399
        int d2 = comb / 20, d3 = comb % 20;
        for (int e = threadIdx.x; e < 768; e += blockDim.x) {
            int r2 = e / 48;
            int c  = e - r2 * 48;
            int m2 = c >> 3, m3 = c & 7;
            float s = 0.f;
#pragma unroll
            for (int r3 = 0; r3 < 16; ++r3) {
                float v2 = core2[((r2 * 20 + d2) * 6 + m2) * 16 + r3]; // [16,20,6,16]
                float v3 = core3[(r3 * 20 + d3) * 8 + m3];             // [16,20,8,1]
                s += v2 * v3;
            }
            g_T23[comb * 768 + r2 * 48 + c] = s;
        }
    }
}

// ---------------------------------------------------------------------------

#define TOK_PER_BLK 8

__device__ __forceinline__ unsigned long long pack_dup(float v) {
    unsigned long long r;
    asm("mov.b64 %0, {%1, %1};" : "=l"(r) : "f"(v));
    return r;
}

__device__ __forceinline__ void fma2(unsigned long long& d,
                                     unsigned long long a,
                                     unsigned long long b) {
    asm("fma.rn.f32x2 %0, %1, %2, %0;" : "+l"(d) : "l"(a), "l"(b));
}

__device__ __forceinline__ void stcs64(float* p, unsigned long long v) {
    asm volatile("st.global.cs.b64 [%0], %1;" :: "l"(p), "l"(v) : "memory");
}

__global__ __launch_bounds__(256, 5)
void te_gather_gemm(const int* __restrict__ x, float* __restrict__ out, int B) {
    __shared__ float sR[TOK_PER_BLK][256];   // [r][a]
    __shared__ float sC[TOK_PER_BLK][768];   // [r][c]

    int w    = threadIdx.x >> 5;
    int lane = threadIdx.x & 31;
    int t    = blockIdx.x * TOK_PER_BLK + w;
    if (t >= B) return;

    int idx = x[t];
    int d0  = idx / 4000;  int rem = idx - d0 * 4000;
    int d1  = rem / 400;   rem -= d1 * 400;
    int d2  = rem / 20;    int d3  = rem - d2 * 20;

    // Stage tables into shared memory through L1 (LDG.128 + STS.128).
    // Table slices recur across tokens -> L1 hits are the fast path here.
    const float4* srcR = (const float4*)&g_T01[(d0 * 10 + d1) * 256];
    const float4* srcC = (const float4*)&g_T23[(d2 * 20 + d3) * 768];
    float4* dR = (float4*)sR[w];
    float4* dC = (float4*)sC[w];
    dR[lane]      = srcR[lane];        // 64 float4 total
    dR[lane + 32] = srcR[lane + 32];
#pragma unroll
    for (int i = 0; i < 6; ++i)        // 192 float4 total
        dC[lane + 32 * i] = srcC[lane + 32 * i];
    __syncwarp();

    // Lane tile: ag = lane>>3 (4 a-rows), cg = lane&7 (6 c-cols)
    int ag = lane >> 3;
    int cg = lane & 7;
    int a0 = ag * 4;
    int c0 = cg * 6;

    // acc[a][p]: 4 a-rows x 3 packed c-pairs (f32x2)
    unsigned long long acc[4][3];
#pragma unroll
    for (int i = 0; i < 4; ++i)
#pragma unroll
        for (int j = 0; j < 3; ++j) acc[i][j] = 0ull;

    const float* baseR = &sR[w][a0];
    const float* baseC = &sC[w][c0];

#pragma unroll
    for (int r = 0; r < 16; ++r) {
        // R: LDS.128, only 4 unique 16B addresses per warp (8-lane broadcast)
        float4 rv = *(const float4*)(baseR + r * 16);
        // C: 3x LDS.64, addresses depend only on lane&7 -> 4-way broadcast
        unsigned long long cv0 = *(const unsigned long long*)(baseC + r * 48);
        unsigned long long cv1 = *(const unsigned long long*)(baseC + r * 48 + 2);
        unsigned long long cv2 = *(const unsigned long long*)(baseC + r * 48 + 4);
        unsigned long long r0 = pack_dup(rv.x);
        unsigned long long r1 = pack_dup(rv.y);
        unsigned long long r2 = pack_dup(rv.z);
        unsigned long long r3 = pack_dup(rv.w);
        fma2(acc[0][0], r0, cv0); fma2(acc[0][1], r0, cv1); fma2(acc[0][2], r0, cv2);
        fma2(acc[1][0], r1, cv0); fma2(acc[1][1], r1, cv1); fma2(acc[1][2], r1, cv2);
        fma2(acc[2][0], r2, cv0); fma2(acc[2][1], r2, cv1); fma2(acc[2][2], r2, cv2);
        fma2(acc[3][0], r3, cv0); fma2(acc[3][1], r3, cv1); fma2(acc[3][2], r3, cv2);
    }

    // Write: out row is 768 contiguous floats; lane covers rows a0..a0+3,
    // cols c0..c0+5 (8-byte aligned streaming stores).
    float* op = out + (size_t)t * 768 + c0;
#pragma unroll
    for (int ai = 0; ai < 4; ++ai) {
        float* rp = op + (a0 + ai) * 48;
        stcs64(rp,     acc[ai][0]);
        stcs64(rp + 2, acc[ai][1]);
        stcs64(rp + 4, acc[ai][2]);
    }
}

// ---------------------------------------------------------------------------

extern "C" void kernel_launch(void* const* d_in, const int* in_sizes, int n_in,
                              void* d_out, int out_size) {
    // Identify inputs by element count (robust to ordering):
    // x: B (=32768), core0: 512, core1: 10240, core2: 30720, core3: 2560
    const int*   x  = nullptr;  int B = 0;
    const float* c0 = nullptr;
    const float* c1 = nullptr;
    const float* c2 = nullptr;
    const float* c3 = nullptr;
    for (int i = 0; i < n_in; ++i) {
        switch (in_sizes[i]) {
            case 512:   c0 = (const float*)d_in[i]; break;
            case 10240: c1 = (const float*)d_in[i]; break;
            case 30720: c2 = (const float*)d_in[i]; break;
            case 2560:  c3 = (const float*)d_in[i]; break;
            default:    x  = (const int*)d_in[i]; B = in_sizes[i]; break;
        }
    }

    precompute_tables<<<480, 256>>>(c0, c1, c2, c3);

    int blocks = (B + TOK_PER_BLK - 1) / TOK_PER_BLK;
    te_gather_gemm<<<blocks, 256>>>(x, (float*)d_out, B);
}

// round 6
// speedup vs baseline: 1.0278x; 1.0278x over previous
#include <cuda_runtime.h>
#include <cuda_bf16.h>

// ---------------------------------------------------------------------------
// TensorizedEmbedding: out[b] = core0[d0] x core1[d1] x core2[d2] x core3[d3]
// ROW_DIMS=(8,10,20,20), COL_DIMS=(4,4,6,8), RANKS=(1,16,16,16,1)
// Strategy: pre-contract into T01[80][16r][16a] and T23[400][16r][48c],
// then per token a 16x48x16 GEMM from shared memory.
// Staging via LDG.128+STS.128 (keeps table slices L1-resident; cp.async.cg
// regressed by forcing the L2 path). Lane tile 4a x 6c (broadcast-heavy
// smem reads), packed f32x2 FMA, streaming output stores.
// ---------------------------------------------------------------------------

static __device__ float g_T01[80 * 256];    // [(d0*10+d1)][r2][a]  (a = m0*4+m1)
static __device__ float g_T23[400 * 768];   // [(d2*20+d3)][r2][c]  (c = m2*8+m3)

// Fused precompute: blocks 0..79 build T01, blocks 80..479 build T23.
__global__ void precompute_tables(const float* __restrict__ core0,
                                  const float* __restrict__ core1,
                                  const float* __restrict__ core2,
                                  const float* __restrict__ core3) {
    if (blockIdx.x < 80) {
        int comb = blockIdx.x;
        int d0 = comb / 10, d1 = comb % 10;
        int e  = threadIdx.x;             // 0..255
        int r2 = e >> 4;
        int a  = e & 15;                  // m0*4 + m1
        int m0 = a >> 2, m1 = a & 3;
        float s = 0.f;
#pragma unroll
        for (int r1 = 0; r1 < 16; ++r1) {
            float v0 = core0[(d0 * 4 + m0) * 16 + r1];             // [1,8,4,16]
            float v1 = core1[((r1 * 10 + d1) * 4 + m1) * 16 + r2]; // [16,10,4,16]
            s += v0 * v1;
        }
        g_T01[comb * 256 + r2 * 16 + a] = s;
    } else {
        int comb = blockIdx.x - 80;       // 0..399
        int d2 = comb / 20, d3 = comb % 20;
        for (int e = threadIdx.x; e < 768; e += blockDim.x) {
            int r2 = e / 48;
            int c  = e - r2 * 48;
            int m2 = c >> 3, m3 = c & 7;
            float s = 0.f;
#pragma unroll
            for (int r3 = 0; r3 < 16; ++r3) {
                float v2 = core2[((r2 * 20 + d2) * 6 + m2) * 16 + r3]; // [16,20,6,16]
                float v3 = core3[(r3 * 20 + d3) * 8 + m3];             // [16,20,8,1]
                s += v2 * v3;
            }
            g_T23[comb * 768 + r2 * 48 + c] = s;
        }
    }
}

// ---------------------------------------------------------------------------

#define TOK_PER_BLK 8

__device__ __forceinline__ unsigned long long pack_dup(float v) {
    unsigned long long r;
    asm("mov.b64 %0, {%1, %1};" : "=l"(r) : "f"(v));
    return r;
}

__device__ __forceinline__ void fma2(unsigned long long& d,
                                     unsigned long long a,
                                     unsigned long long b) {
    asm("fma.rn.f32x2 %0, %1, %2, %0;" : "+l"(d) : "l"(a), "l"(b));
}

__device__ __forceinline__ void stcs64(float* p, unsigned long long v) {
    asm volatile("st.global.cs.b64 [%0], %1;" :: "l"(p), "l"(v) : "memory");
}

__global__ __launch_bounds__(256, 5)
void te_gather_gemm(const int* __restrict__ x, float* __restrict__ out, int B) {
    __shared__ float sR[TOK_PER_BLK][256];   // [r][a]
    __shared__ float sC[TOK_PER_BLK][768];   // [r][c]

    int w    = threadIdx.x >> 5;
    int lane = threadIdx.x & 31;
    int t    = blockIdx.x * TOK_PER_BLK + w;
    if (t >= B) return;

    int idx = x[t];
    int d0  = idx / 4000;  int rem = idx - d0 * 4000;
    int d1  = rem / 400;   rem -= d1 * 400;
    int d2  = rem / 20;    int d3  = rem - d2 * 20;

    // Stage tables into shared memory through L1 (LDG.128 + STS.128).
    // Table slices recur across tokens -> L1 hits are the fast path here.
    const float4* srcR = (const float4*)&g_T01[(d0 * 10 + d1) * 256];
    const float4* srcC = (const float4*)&g_T23[(d2 * 20 + d3) * 768];
    float4* dR = (float4*)sR[w];
    float4* dC = (float4*)sC[w];
    dR[lane]      = srcR[lane];        // 64 float4 total
    dR[lane + 32] = srcR[lane + 32];
#pragma unroll
    for (int i = 0; i < 6; ++i)        // 192 float4 total
        dC[lane + 32 * i] = srcC[lane + 32 * i];
    __syncwarp();

    // Lane tile: ag = lane>>3 (4 a-rows), cg = lane&7 (6 c-cols)
    int ag = lane >> 3;
    int cg = lane & 7;
    int a0 = ag * 4;
    int c0 = cg * 6;

    // acc[a][p]: 4 a-rows x 3 packed c-pairs (f32x2)
    unsigned long long acc[4][3];
#pragma unroll
    for (int i = 0; i < 4; ++i)
#pragma unroll
        for (int j = 0; j < 3; ++j) acc[i][j] = 0ull;

    const float* baseR = &sR[w][a0];
    const float* baseC = &sC[w][c0];

#pragma unroll
    for (int r = 0; r < 16; ++r) {
        // R: LDS.128, only 4 unique 16B addresses per warp (8-lane broadcast)
        float4 rv = *(const float4*)(baseR + r * 16);
        // C: 3x LDS.64, addresses depend only on lane&7 -> 4-way broadcast
        unsigned long long cv0 = *(const unsigned long long*)(baseC + r * 48);
        unsigned long long cv1 = *(const unsigned long long*)(baseC + r * 48 + 2);
        unsigned long long cv2 = *(const unsigned long long*)(baseC + r * 48 + 4);
        unsigned long long r0 = pack_dup(rv.x);
        unsigned long long r1 = pack_dup(rv.y);
        unsigned long long r2 = pack_dup(rv.z);
        unsigned long long r3 = pack_dup(rv.w);
        fma2(acc[0][0], r0, cv0); fma2(acc[0][1], r0, cv1); fma2(acc[0][2], r0, cv2);
        fma2(acc[1][0], r1, cv0); fma2(acc[1][1], r1, cv1); fma2(acc[1][2], r1, cv2);
        fma2(acc[2][0], r2, cv0); fma2(acc[2][1], r2, cv1); fma2(acc[2][2], r2, cv2);
        fma2(acc[3][0], r3, cv0); fma2(acc[3][1], r3, cv1); fma2(acc[3][2], r3, cv2);
    }

    // Write: out row is 768 contiguous floats; lane covers rows a0..a0+3,
    // cols c0..c0+5 (8-byte aligned streaming stores).
    float* op = out + (size_t)t * 768 + c0;
#pragma unroll
    for (int ai = 0; ai < 4; ++ai) {
        float* rp = op + (a0 + ai) * 48;
        stcs64(rp,     acc[ai][0]);
        stcs64(rp + 2, acc[ai][1]);
        stcs64(rp + 4, acc[ai][2]);
    }
}

// ---------------------------------------------------------------------------

extern "C" void kernel_launch(void* const* d_in, const int* in_sizes, int n_in,
                              void* d_out, int out_size) {
    // Identify inputs by element count (robust to ordering):
    // x: B (=32768), core0: 512, core1: 10240, core2: 30720, core3: 2560
    const int*   x  = nullptr;  int B = 0;
    const float* c0 = nullptr;
    const float* c1 = nullptr;
    const float* c2 = nullptr;
    const float* c3 = nullptr;
    for (int i = 0; i < n_in; ++i) {
        switch (in_sizes[i]) {
            case 512:   c0 = (const float*)d_in[i]; break;
            case 10240: c1 = (const float*)d_in[i]; break;
            case 30720: c2 = (const float*)d_in[i]; break;
            case 2560:  c3 = (const float*)d_in[i]; break;
            default:    x  = (const int*)d_in[i]; B = in_sizes[i]; break;
        }
    }

    precompute_tables<<<480, 256>>>(c0, c1, c2, c3);

    int blocks = (B + TOK_PER_BLK - 1) / TOK_PER_BLK;
    te_gather_gemm<<<blocks, 256>>>(x, (float*)d_out, B);
}

// round 7
// speedup vs baseline: 1.3161x; 1.2806x over previous
#include <cuda_runtime.h>
#include <cuda_bf16.h>

// ---------------------------------------------------------------------------
// TensorizedEmbedding: out[b] = core0[d0] x core1[d1] x core2[d2] x core3[d3]
// ROW_DIMS=(8,10,20,20), COL_DIMS=(4,4,6,8), RANKS=(1,16,16,16,1)
// Strategy: pre-contract into T01[80][16r][16a] and T23[400][16r][48c],
// then per token a 16x48x16 GEMM.
// Key finding (R4/R6): occupancy>4 blocks/SM shrinks L1D below what the
// gathered T23 slices need -> L2-bound regression. So: occ=4, minimal smem.
// C staged to SMEM via LDG.128+STS.128 (through L1); R read directly from
// global (T01 is 80KB, fully L1-resident). Lane tile 4a x 6c, f32x2 FMA.
// ---------------------------------------------------------------------------

static __device__ float g_T01[80 * 256];    // [(d0*10+d1)][r2][a]  (a = m0*4+m1)
static __device__ float g_T23[400 * 768];   // [(d2*20+d3)][r2][c]  (c = m2*8+m3)

// Fused precompute: blocks 0..79 build T01, blocks 80..479 build T23.
__global__ void precompute_tables(const float* __restrict__ core0,
                                  const float* __restrict__ core1,
                                  const float* __restrict__ core2,
                                  const float* __restrict__ core3) {
    if (blockIdx.x < 80) {
        int comb = blockIdx.x;
        int d0 = comb / 10, d1 = comb % 10;
        int e  = threadIdx.x;             // 0..255
        int r2 = e >> 4;
        int a  = e & 15;                  // m0*4 + m1
        int m0 = a >> 2, m1 = a & 3;
        float s = 0.f;
#pragma unroll
        for (int r1 = 0; r1 < 16; ++r1) {
            float v0 = core0[(d0 * 4 + m0) * 16 + r1];             // [1,8,4,16]
            float v1 = core1[((r1 * 10 + d1) * 4 + m1) * 16 + r2]; // [16,10,4,16]
            s += v0 * v1;
        }
        g_T01[comb * 256 + r2 * 16 + a] = s;
    } else {
        int comb = blockIdx.x - 80;       // 0..399
        int d2 = comb / 20, d3 = comb % 20;
        for (int e = threadIdx.x; e < 768; e += blockDim.x) {
            int r2 = e / 48;
            int c  = e - r2 * 48;
            int m2 = c >> 3, m3 = c & 7;
            float s = 0.f;
#pragma unroll
            for (int r3 = 0; r3 < 16; ++r3) {
                float v2 = core2[((r2 * 20 + d2) * 6 + m2) * 16 + r3]; // [16,20,6,16]
                float v3 = core3[(r3 * 20 + d3) * 8 + m3];             // [16,20,8,1]
                s += v2 * v3;
            }
            g_T23[comb * 768 + r2 * 48 + c] = s;
        }
    }
}

// ---------------------------------------------------------------------------

#define TOK_PER_BLK 8

__device__ __forceinline__ unsigned long long pack_dup(float v) {
    unsigned long long r;
    asm("mov.b64 %0, {%1, %1};" : "=l"(r) : "f"(v));
    return r;
}

__device__ __forceinline__ void fma2(unsigned long long& d,
                                     unsigned long long a,
                                     unsigned long long b) {
    asm("fma.rn.f32x2 %0, %1, %2, %0;" : "+l"(d) : "l"(a), "l"(b));
}

__device__ __forceinline__ void stcs64(float* p, unsigned long long v) {
    asm volatile("st.global.cs.b64 [%0], %1;" :: "l"(p), "l"(v) : "memory");
}

__global__ __launch_bounds__(256, 4)
void te_gather_gemm(const int* __restrict__ x, float* __restrict__ out, int B) {
    __shared__ float sC[TOK_PER_BLK][768];   // [r][c]  (24KB/block)

    int w    = threadIdx.x >> 5;
    int lane = threadIdx.x & 31;
    int t    = blockIdx.x * TOK_PER_BLK + w;
    if (t >= B) return;

    int idx = x[t];
    int d0  = idx / 4000;  int rem = idx - d0 * 4000;
    int d1  = rem / 400;   rem -= d1 * 400;
    int d2  = rem / 20;    int d3  = rem - d2 * 20;

    // Stage C into shared memory through L1 (LDG.128 + STS.128).
    const float4* srcC = (const float4*)&g_T23[(d2 * 20 + d3) * 768];
    float4* dC = (float4*)sC[w];
#pragma unroll
    for (int i = 0; i < 6; ++i)        // 192 float4 total
        dC[lane + 32 * i] = srcC[lane + 32 * i];
    __syncwarp();

    // Lane tile: ag = lane>>3 (4 a-rows), cg = lane&7 (6 c-cols)
    int ag = lane >> 3;
    int cg = lane & 7;
    int a0 = ag * 4;
    int c0 = cg * 6;

    // acc[a][p]: 4 a-rows x 3 packed c-pairs (f32x2)
    unsigned long long acc[4][3];
#pragma unroll
    for (int i = 0; i < 4; ++i)
#pragma unroll
        for (int j = 0; j < 3; ++j) acc[i][j] = 0ull;

    // R read directly from global: T01 slice base (L1-resident, 80KB table).
    const float4* baseR = (const float4*)&g_T01[(d0 * 10 + d1) * 256 + a0];
    const float*  baseC = &sC[w][c0];

#pragma unroll
    for (int r = 0; r < 16; ++r) {
        // R: LDG.128 L1-hit, 4 unique 16B addrs per warp (64B coalesced)
        float4 rv = __ldg(baseR + r * 4);
        // C: 3x LDS.64, bank-conflict-free, 4-way broadcast
        unsigned long long cv0 = *(const unsigned long long*)(baseC + r * 48);
        unsigned long long cv1 = *(const unsigned long long*)(baseC + r * 48 + 2);
        unsigned long long cv2 = *(const unsigned long long*)(baseC + r * 48 + 4);
        unsigned long long r0 = pack_dup(rv.x);
        unsigned long long r1 = pack_dup(rv.y);
        unsigned long long r2 = pack_dup(rv.z);
        unsigned long long r3 = pack_dup(rv.w);
        fma2(acc[0][0], r0, cv0); fma2(acc[0][1], r0, cv1); fma2(acc[0][2], r0, cv2);
        fma2(acc[1][0], r1, cv0); fma2(acc[1][1], r1, cv1); fma2(acc[1][2], r1, cv2);
        fma2(acc[2][0], r2, cv0); fma2(acc[2][1], r2, cv1); fma2(acc[2][2], r2, cv2);
        fma2(acc[3][0], r3, cv0); fma2(acc[3][1], r3, cv1); fma2(acc[3][2], r3, cv2);
    }

    // Write: out row is 768 contiguous floats; lane covers rows a0..a0+3,
    // cols c0..c0+5 (8-byte aligned streaming stores).
    float* op = out + (size_t)t * 768 + c0;
#pragma unroll
    for (int ai = 0; ai < 4; ++ai) {
        float* rp = op + (a0 + ai) * 48;
        stcs64(rp,     acc[ai][0]);
        stcs64(rp + 2, acc[ai][1]);
        stcs64(rp + 4, acc[ai][2]);
    }
}

// ---------------------------------------------------------------------------

extern "C" void kernel_launch(void* const* d_in, const int* in_sizes, int n_in,
                              void* d_out, int out_size) {
    // Identify inputs by element count (robust to ordering):
    // x: B (=32768), core0: 512, core1: 10240, core2: 30720, core3: 2560
    const int*   x  = nullptr;  int B = 0;
    const float* c0 = nullptr;
    const float* c1 = nullptr;
    const float* c2 = nullptr;
    const float* c3 = nullptr;
    for (int i = 0; i < n_in; ++i) {
        switch (in_sizes[i]) {
            case 512:   c0 = (const float*)d_in[i]; break;
            case 10240: c1 = (const float*)d_in[i]; break;
            case 30720: c2 = (const float*)d_in[i]; break;
            case 2560:  c3 = (const float*)d_in[i]; break;
            default:    x  = (const int*)d_in[i]; B = in_sizes[i]; break;
        }
    }

    precompute_tables<<<480, 256>>>(c0, c1, c2, c3);

    int blocks = (B + TOK_PER_BLK - 1) / TOK_PER_BLK;
    te_gather_gemm<<<blocks, 256>>>(x, (float*)d_out, B);
}

// round 8
// speedup vs baseline: 1.3943x; 1.0594x over previous
#include <cuda_runtime.h>
#include <cuda_bf16.h>

// ---------------------------------------------------------------------------
// TensorizedEmbedding: out[b] = core0[d0] x core1[d1] x core2[d2] x core3[d3]
// ROW_DIMS=(8,10,20,20), COL_DIMS=(4,4,6,8), RANKS=(1,16,16,16,1)
// Strategy: pre-contract into T01[80][16r][16a] and T23[400][16r][48c],
// then per token a 16x48x16 GEMM from shared memory.
// Config (from R3..R7 matrix): stage BOTH tables via LDG.128+STS.128
// (through L1), occupancy capped at 4 blocks/SM (protects L1D carveout),
// lane tile 4a x 6c whose smem reads are broadcast-heavy (R: 4 unique
// addrs/warp; C: 8 unique, bank-disjoint) -> ~2x fewer L1 wavefronts than
// the 2a x 12c tile. Packed f32x2 FMA, streaming .cs output stores.
// ---------------------------------------------------------------------------

static __device__ float g_T01[80 * 256];    // [(d0*10+d1)][r2][a]  (a = m0*4+m1)
static __device__ float g_T23[400 * 768];   // [(d2*20+d3)][r2][c]  (c = m2*8+m3)

// Fused precompute: blocks 0..79 build T01, blocks 80..479 build T23.
__global__ void precompute_tables(const float* __restrict__ core0,
                                  const float* __restrict__ core1,
                                  const float* __restrict__ core2,
                                  const float* __restrict__ core3) {
    if (blockIdx.x < 80) {
        int comb = blockIdx.x;
        int d0 = comb / 10, d1 = comb % 10;
        int e  = threadIdx.x;             // 0..255
        int r2 = e >> 4;
        int a  = e & 15;                  // m0*4 + m1
        int m0 = a >> 2, m1 = a & 3;
        float s = 0.f;
#pragma unroll
        for (int r1 = 0; r1 < 16; ++r1) {
            float v0 = core0[(d0 * 4 + m0) * 16 + r1];             // [1,8,4,16]
            float v1 = core1[((r1 * 10 + d1) * 4 + m1) * 16 + r2]; // [16,10,4,16]
            s += v0 * v1;
        }
        g_T01[comb * 256 + r2 * 16 + a] = s;
    } else {
        int comb = blockIdx.x - 80;       // 0..399
        int d2 = comb / 20, d3 = comb % 20;
        for (int e = threadIdx.x; e < 768; e += blockDim.x) {
            int r2 = e / 48;
            int c  = e - r2 * 48;
            int m2 = c >> 3, m3 = c & 7;
            float s = 0.f;
#pragma unroll
            for (int r3 = 0; r3 < 16; ++r3) {
                float v2 = core2[((r2 * 20 + d2) * 6 + m2) * 16 + r3]; // [16,20,6,16]
                float v3 = core3[(r3 * 20 + d3) * 8 + m3];             // [16,20,8,1]
                s += v2 * v3;
            }
            g_T23[comb * 768 + r2 * 48 + c] = s;
        }
    }
}

// ---------------------------------------------------------------------------

#define TOK_PER_BLK 8

__device__ __forceinline__ unsigned long long pack_dup(float v) {
    unsigned long long r;
    asm("mov.b64 %0, {%1, %1};" : "=l"(r) : "f"(v));
    return r;
}

__device__ __forceinline__ void fma2(unsigned long long& d,
                                     unsigned long long a,
                                     unsigned long long b) {
    asm("fma.rn.f32x2 %0, %1, %2, %0;" : "+l"(d) : "l"(a), "l"(b));
}

__device__ __forceinline__ void stcs64(float* p, unsigned long long v) {
    asm volatile("st.global.cs.b64 [%0], %1;" :: "l"(p), "l"(v) : "memory");
}

__global__ __launch_bounds__(256, 4)
void te_gather_gemm(const int* __restrict__ x, float* __restrict__ out, int B) {
    __shared__ float sR[TOK_PER_BLK][256];   // [r][a]  (8KB)
    __shared__ float sC[TOK_PER_BLK][768];   // [r][c]  (24KB)

    int w    = threadIdx.x >> 5;
    int lane = threadIdx.x & 31;
    int t    = blockIdx.x * TOK_PER_BLK + w;
    if (t >= B) return;

    int idx = x[t];
    int d0  = idx / 4000;  int rem = idx - d0 * 4000;
    int d1  = rem / 400;   rem -= d1 * 400;
    int d2  = rem / 20;    int d3  = rem - d2 * 20;

    // Stage both tables into shared memory through L1 (LDG.128 + STS.128).
    // Table slices recur across tokens -> L1 hits are the fast path here.
    const float4* srcR = (const float4*)&g_T01[(d0 * 10 + d1) * 256];
    const float4* srcC = (const float4*)&g_T23[(d2 * 20 + d3) * 768];
    float4* dR = (float4*)sR[w];
    float4* dC = (float4*)sC[w];
    dR[lane]      = srcR[lane];        // 64 float4 total
    dR[lane + 32] = srcR[lane + 32];
#pragma unroll
    for (int i = 0; i < 6; ++i)        // 192 float4 total
        dC[lane + 32 * i] = srcC[lane + 32 * i];
    __syncwarp();

    // Lane tile: ag = lane>>3 (4 a-rows), cg = lane&7 (6 c-cols)
    int ag = lane >> 3;
    int cg = lane & 7;
    int a0 = ag * 4;
    int c0 = cg * 6;

    // acc[a][p]: 4 a-rows x 3 packed c-pairs (f32x2)
    unsigned long long acc[4][3];
#pragma unroll
    for (int i = 0; i < 4; ++i)
#pragma unroll
        for (int j = 0; j < 3; ++j) acc[i][j] = 0ull;

    const float* baseR = &sR[w][a0];
    const float* baseC = &sC[w][c0];

#pragma unroll
    for (int r = 0; r < 16; ++r) {
        // R: LDS.128, only 4 unique 16B addrs per warp (8-lane broadcast)
        float4 rv = *(const float4*)(baseR + r * 16);
        // C: 3x LDS.64, 8 unique addrs (4-way broadcast), bank-disjoint
        unsigned long long cv0 = *(const unsigned long long*)(baseC + r * 48);
        unsigned long long cv1 = *(const unsigned long long*)(baseC + r * 48 + 2);
        unsigned long long cv2 = *(const unsigned long long*)(baseC + r * 48 + 4);
        unsigned long long r0 = pack_dup(rv.x);
        unsigned long long r1 = pack_dup(rv.y);
        unsigned long long r2 = pack_dup(rv.z);
        unsigned long long r3 = pack_dup(rv.w);
        fma2(acc[0][0], r0, cv0); fma2(acc[0][1], r0, cv1); fma2(acc[0][2], r0, cv2);
        fma2(acc[1][0], r1, cv0); fma2(acc[1][1], r1, cv1); fma2(acc[1][2], r1, cv2);
        fma2(acc[2][0], r2, cv0); fma2(acc[2][1], r2, cv1); fma2(acc[2][2], r2, cv2);
        fma2(acc[3][0], r3, cv0); fma2(acc[3][1], r3, cv1); fma2(acc[3][2], r3, cv2);
    }

    // Write: out row is 768 contiguous floats; lane covers rows a0..a0+3,
    // cols c0..c0+5 (8-byte aligned streaming stores).
    float* op = out + (size_t)t * 768 + c0;
#pragma unroll
    for (int ai = 0; ai < 4; ++ai) {
        float* rp = op + (a0 + ai) * 48;
        stcs64(rp,     acc[ai][0]);
        stcs64(rp + 2, acc[ai][1]);
        stcs64(rp + 4, acc[ai][2]);
    }
}

// ---------------------------------------------------------------------------

extern "C" void kernel_launch(void* const* d_in, const int* in_sizes, int n_in,
                              void* d_out, int out_size) {
    // Identify inputs by element count (robust to ordering):
    // x: B (=32768), core0: 512, core1: 10240, core2: 30720, core3: 2560
    const int*   x  = nullptr;  int B = 0;
    const float* c0 = nullptr;
    const float* c1 = nullptr;
    const float* c2 = nullptr;
    const float* c3 = nullptr;
    for (int i = 0; i < n_in; ++i) {
        switch (in_sizes[i]) {
            case 512:   c0 = (const float*)d_in[i]; break;
            case 10240: c1 = (const float*)d_in[i]; break;
            case 30720: c2 = (const float*)d_in[i]; break;
            case 2560:  c3 = (const float*)d_in[i]; break;
            default:    x  = (const int*)d_in[i]; B = in_sizes[i]; break;
        }
    }

    precompute_tables<<<480, 256>>>(c0, c1, c2, c3);

    int blocks = (B + TOK_PER_BLK - 1) / TOK_PER_BLK;
    te_gather_gemm<<<blocks, 256>>>(x, (float*)d_out, B);
}